// round 7
// baseline (speedup 1.0000x reference)
#include <cuda_runtime.h>

// HarmonicLowering: out[b, k*C+ch, f, t] = w * x[b,ch,idx,t] + (1-w) * x[b,ch,idx1,t]
//   prod = f*(k+1); idx = prod>>2; w = 1 - (prod&3)*0.25
//   w<1 implies idx<=191 so idx+1 needs no clamp; w==1 -> alias idx1=idx
//   (same-address load, L1 hit, result unaffected).
// B=8, C=32, F=256, T=512, K=4. All powers of two -> shift/mask decode.

#define BATCH 8
#define CH    32
#define FREQ  256
#define TIME  512
#define KTAPS 4

#define T4       (TIME / 4)                          // 128 float4 per time-row
#define OUT_E4   (BATCH * KTAPS * CH * FREQ * T4)    // 33,554,432
#define VPT      4                                   // outputs per thread

__global__ __launch_bounds__(256)
void harmonic_lowering_kernel(const float4* __restrict__ x, float4* __restrict__ out)
{
    const unsigned int ibase = blockIdx.x * (256u * VPT) + threadIdx.x;

    unsigned int off0[VPT], off1[VPT];
    float        w[VPT];

    #pragma unroll
    for (int j = 0; j < VPT; j++) {
        unsigned int i  = ibase + j * 256u;
        unsigned int t4 = i & (T4 - 1);
        unsigned int f  = (i >> 7) & (FREQ - 1);
        unsigned int kc = (i >> 15) & 127u;
        unsigned int b  = i >> 22;
        unsigned int prod = f * ((kc >> 5) + 1u);
        unsigned int frac = prod & 3u;
        unsigned int idx  = prod >> 2;
        unsigned int idx1 = frac ? (idx + 1u) : idx;
        w[j] = 1.0f - (float)frac * 0.25f;
        unsigned int base = ((b * CH + (kc & 31u)) * FREQ) * T4 + t4;
        off0[j] = base + idx  * T4;
        off1[j] = base + idx1 * T4;
    }

    // front-batched: 8 independent LDG.128 in flight
    float4 g0[VPT], g1[VPT];
    #pragma unroll
    for (int j = 0; j < VPT; j++) g0[j] = x[off0[j]];
    #pragma unroll
    for (int j = 0; j < VPT; j++) g1[j] = x[off1[j]];

    #pragma unroll
    for (int j = 0; j < VPT; j++) {
        float4 r;
        r.x = fmaf(w[j], g0[j].x - g1[j].x, g1[j].x);
        r.y = fmaf(w[j], g0[j].y - g1[j].y, g1[j].y);
        r.z = fmaf(w[j], g0[j].z - g1[j].z, g1[j].z);
        r.w = fmaf(w[j], g0[j].w - g1[j].w, g1[j].w);
        __stcs(&out[ibase + j * 256u], r);   // evict-first: keep L2 for reused input
    }
}

extern "C" void kernel_launch(void* const* d_in, const int* in_sizes, int n_in,
                              void* d_out, int out_size)
{
    (void)in_sizes; (void)n_in; (void)out_size;
    const float4* x = (const float4*)d_in[0];
    float4* out = (float4*)d_out;

    const int threads = 256;
    const int blocks  = OUT_E4 / (threads * VPT);   // 32768, exact
    harmonic_lowering_kernel<<<blocks, threads>>>(x, out);
}